// round 14
// baseline (speedup 1.0000x reference)
#include <cuda_runtime.h>
#include <cuda_bf16.h>
#include <cstdint>
#include <math_constants.h>

#define B_ 64
#define L_ 1024
#define P_ 2047
#define NS 16
#define SBI 272                 // interleaved tile row stride (bytes)
#define TI  (64 * SBI)          // 17408 B per 64-row tile
#define GS  68                  // ring row stride (floats)
#define GSZ (64 * GS)

// smem slots: V ping-pongs through the (dead after prologue) Q and R slots
#define O_VA 0                  // Q tile during prologue, then V buffer 0
#define O_R  TI                 // R tile during prologue, then V buffer 1
#define O_K  (2 * TI)
#define O_P  (3 * TI)
#define O_G  (4 * TI)           // ring: 2 slots x 64 rows x GS floats
#define SMEMB (4 * TI + 2 * GSZ * 4)   // 104448 B -> 2 CTAs/SM

__device__ float g_S[B_ * L_];  // per-row softmax denominators for the normalize pass

__device__ __forceinline__ uint32_t smem_u32(const void* p) {
    uint32_t a;
    asm("{ .reg .u64 t; cvta.to.shared.u64 t, %1; cvt.u32.u64 %0, t; }" : "=r"(a) : "l"(p));
    return a;
}
#define LDSM4(r, a) \
    asm volatile("ldmatrix.sync.aligned.m8n8.x4.shared.b16 {%0,%1,%2,%3}, [%4];" \
        : "=r"((r)[0]), "=r"((r)[1]), "=r"((r)[2]), "=r"((r)[3]) : "r"(a))
#define LDSM4T(r, a) \
    asm volatile("ldmatrix.sync.aligned.m8n8.x4.trans.shared.b16 {%0,%1,%2,%3}, [%4];" \
        : "=r"((r)[0]), "=r"((r)[1]), "=r"((r)[2]), "=r"((r)[3]) : "r"(a))
#define MMA(c, a, b) \
    asm volatile("mma.sync.aligned.m16n8k16.row.col.f32.bf16.bf16.f32 " \
        "{%0,%1,%2,%3}, {%4,%5,%6,%7}, {%8,%9}, {%0,%1,%2,%3};" \
        : "+f"((c)[0]), "+f"((c)[1]), "+f"((c)[2]), "+f"((c)[3]) \
        : "r"((a)[0]), "r"((a)[1]), "r"((a)[2]), "r"((a)[3]), "r"((b)[0]), "r"((b)[1]))

__device__ __forceinline__ uint32_t pk2(float a, float b) {
    return (uint32_t)__bfloat16_as_ushort(__float2bfloat16(a)) |
           ((uint32_t)__bfloat16_as_ushort(__float2bfloat16(b)) << 16);
}
__device__ __forceinline__ float bfres(float x) {
    return x - __bfloat162float(__float2bfloat16(x));
}
__device__ __forceinline__ void st_blk(char* sm, int oT, int r, int bl, float4 a, float4 b) {
    uint4 hi = make_uint4(pk2(a.x, a.y), pk2(a.z, a.w), pk2(b.x, b.y), pk2(b.z, b.w));
    uint4 lo = make_uint4(pk2(bfres(a.x), bfres(a.y)), pk2(bfres(a.z), bfres(a.w)),
                          pk2(bfres(b.x), bfres(b.y)), pk2(bfres(b.z), bfres(b.w)));
    char* p = sm + oT + r * SBI + bl * 32;
    *(uint4*)p = hi;
    *(uint4*)(p + 16) = lo;
}

__global__ __launch_bounds__(256, 2)
void fused_fa_kernel(const float* __restrict__ q, const float* __restrict__ kk,
                     const float* __restrict__ v, const float* __restrict__ pos,
                     const char* __restrict__ maskp, float* __restrict__ out,
                     float* __restrict__ attn) {
    extern __shared__ char sm[];
    const uint32_t sb = smem_u32(sm);
    const int tid = threadIdx.x;
    const int lane = tid & 31, w = tid >> 5;
    const bool isS = (w < 4);          // 4 S-warps (QK^T+epi+PV), 4 G-warps (bias gemm)
    const int wr = w & 3;              // row group (16 rows) for both roles
    const int b = blockIdx.y, l0 = blockIdx.x * 64;

    const float* qb = q + (size_t)b * L_ * 64;
    const float* kb = kk + (size_t)b * L_ * 64;
    const float* vb = v + (size_t)b * L_ * 64;
    const float* pb = pos + (size_t)b * P_ * 64;

    float* ring = (float*)(sm + O_G);
    int* cnt = (int*)(sm + O_G);       // overlaid; consumed before first ring write

    // ---- mask dtype detection (first 8KB) ----
    if (tid < 2) cnt[tid] = 0;
    __syncthreads();
    {
        int c0 = 0, c1 = 0;
        #pragma unroll
        for (int e = 0; e < 2; e++) {
            uint4 u = ((const uint4*)maskp)[tid * 2 + e];
            uint32_t ws[4] = {u.x, u.y, u.z, u.w};
            #pragma unroll
            for (int wd = 0; wd < 4; wd++) {
                c0 += ((ws[wd] & 0x000000ffu) != 0);
                c1 += ((ws[wd] & 0x0000ff00u) != 0);
            }
        }
        if (c0) atomicAdd(&cnt[0], c0);
        if (c1) atomicAdd(&cnt[1], c1);
    }

    // ---- fills (512 tasks of 8 contiguous k-elems over 256 threads) ----
    auto fill_K = [&](int t) {
        #pragma unroll
        for (int e = 0; e < 2; e++) {
            int tt = tid + e * 256, r = tt & 63, bl = tt >> 6;
            const float* ap = kb + (size_t)(t * 64 + r) * 64 + bl * 8;
            st_blk(sm, O_K, r, bl, *(const float4*)ap, *(const float4*)(ap + 4));
        }
    };
    auto fill_V = [&](int t) {
        int oT = (t & 1) ? O_R : O_VA;
        #pragma unroll
        for (int e = 0; e < 2; e++) {
            int tt = tid + e * 256, r = tt & 63, bl = tt >> 6;
            const float* ap = vb + (size_t)(t * 64 + r) * 64 + bl * 8;
            st_blk(sm, oT, r, bl, *(const float4*)ap, *(const float4*)(ap + 4));
        }
    };
    auto fill_P = [&](int win) {
        #pragma unroll
        for (int e = 0; e < 2; e++) {
            int tt = tid + e * 256, r = tt & 63, bl = tt >> 6;
            int pr = l0 + 64 * win + r; if (pr > P_ - 1) pr = P_ - 1;
            const float* ap = pb + (size_t)pr * 64 + bl * 8;
            st_blk(sm, O_P, r, bl, *(const float4*)ap, *(const float4*)(ap + 4));
        }
    };

    // prologue fills: Q->O_VA, R->O_R (scaled 1/8), K0, P win0
    #pragma unroll
    for (int e = 0; e < 2; e++) {
        int tt = tid + e * 256, r = tt & 63, bl = tt >> 6;
        const float* ap = qb + (size_t)(l0 + r) * 64 + bl * 8;
        float4 a0 = *(const float4*)ap, a1 = *(const float4*)(ap + 4);
        a0.x *= .125f; a0.y *= .125f; a0.z *= .125f; a0.w *= .125f;
        a1.x *= .125f; a1.y *= .125f; a1.z *= .125f; a1.w *= .125f;
        st_blk(sm, O_VA, r, bl, a0, a1);
        const float* rp = qb + (size_t)(L_ - 1 - (l0 + r)) * 64 + bl * 8;
        float4 r0v = *(const float4*)rp, r1v = *(const float4*)(rp + 4);
        r0v.x *= .125f; r0v.y *= .125f; r0v.z *= .125f; r0v.w *= .125f;
        r1v.x *= .125f; r1v.y *= .125f; r1v.z *= .125f; r1v.w *= .125f;
        st_blk(sm, O_R, r, bl, r0v, r1v);
    }
    fill_K(0); fill_P(0);
    __syncthreads();
    const int mode = (cnt[0] > 0 && cnt[1] > 0) ? 0 : 1;

    auto adA = [&](int oT, int kc, int hi) -> uint32_t {
        int row = 16 * wr + (lane & 15), blk = 2 * kc + (lane >> 4);
        return sb + oT + row * SBI + blk * 32 + (hi ? 0 : 16);
    };
    auto adB = [&](int oT, int np, int kc, int hi) -> uint32_t {
        int nrow = 16 * np + 8 * (lane >> 4) + (lane & 7);
        int blk = 2 * kc + ((lane >> 3) & 1);
        return sb + oT + nrow * SBI + blk * 32 + (hi ? 0 : 16);
    };
    auto adBT = [&](int oT, int np, int kc, int hi) -> uint32_t {
        int krow = 16 * kc + (lane & 15);
        int blk = 2 * np + (lane >> 4);
        return sb + oT + krow * SBI + blk * 32 + (hi ? 0 : 16);
    };
    const int r0 = 16 * wr + (lane >> 2), c2 = lane & 3;

    // persistent A fragments: S-warps cache Q (from O_VA), G-warps cache R
    uint32_t Ah[4][4], Al[4][4];
    {
        int oT = isS ? O_VA : O_R;
        #pragma unroll
        for (int kc = 0; kc < 4; kc++) { LDSM4(Ah[kc], adA(oT, kc, 1)); LDSM4(Al[kc], adA(oT, kc, 0)); }
    }

    float accA[8][4];                      // accS (S-warps) / accG (G-warps)
    float accO[8][4] = {};                 // S-warps only
    float run_s[2] = {0.f, 0.f};

    // m16n64k64 3-term split GEMM: acc += Ah*Bh + Al*Bh + Ah*Bl
    auto gemm64 = [&](int oB, float acc[8][4]) {
        #pragma unroll
        for (int kc = 0; kc < 4; kc++)
            #pragma unroll
            for (int np = 0; np < 4; np++) {
                uint32_t bh[4], bl_[4];
                LDSM4(bh, adB(oB, np, kc, 1));
                MMA(acc[2 * np], Ah[kc], bh);     MMA(acc[2 * np], Al[kc], bh);
                MMA(acc[2 * np + 1], Ah[kc], bh + 2); MMA(acc[2 * np + 1], Al[kc], bh + 2);
                LDSM4(bl_, adB(oB, np, kc, 0));
                MMA(acc[2 * np], Ah[kc], bl_);    MMA(acc[2 * np + 1], Ah[kc], bl_ + 2);
            }
    };
    auto ring_store = [&](int slot) {       // G-warps: rows 16wr..16wr+15, cols 0..63
        float* gn = ring + slot * GSZ;
        #pragma unroll
        for (int nf = 0; nf < 8; nf++) {
            int j0 = 8 * nf + 2 * c2;
            #pragma unroll
            for (int h = 0; h < 2; h++) {
                int i = r0 + 8 * h;
                *(float2*)(gn + i * GS + j0) = make_float2(accA[nf][2 * h], accA[nf][2 * h + 1]);
            }
        }
    };

    // ---- prologue G(0) ----
    if (!isS) {
        #pragma unroll
        for (int nf = 0; nf < 8; nf++)
            #pragma unroll
            for (int e = 0; e < 4; e++) accA[nf][e] = 0.f;
        gemm64(O_P, accA);
    }
    __syncthreads();                        // Q/R frags built, P consumed -> slots free
    if (!isS) ring_store(0);
    fill_P(1);
    fill_V(0);                               // into O_VA (Q slot, now dead)
    __syncthreads();

    // ================= main loop =================
    for (int t = 0; t < NS; t++) {
        #pragma unroll
        for (int nf = 0; nf < 8; nf++)
            #pragma unroll
            for (int e = 0; e < 4; e++) accA[nf][e] = 0.f;
        if (isS) gemm64(O_K, accA);          // S(t)
        else     gemm64(O_P, accA);          // G(t+1)
        __syncthreads();                     // K, P consumed
        if (!isS) ring_store((t + 1) & 1);
        if (t < NS - 1) { fill_K(t + 1); fill_V(t + 1); }
        fill_P(t + 2);
        __syncthreads();                     // ring slot t+1 + new tiles visible
        if (isS) {
            // epilogue: bias + mask + logit store + exp + pack p (= exp(x), no max needed)
            const float* gc = ring + (t & 1) * GSZ;
            const float* gn = ring + ((t + 1) & 1) * GSZ;
            uint32_t Ph[4][4], Pl[4][4];
            #pragma unroll
            for (int nf = 0; nf < 8; nf++) {
                int j0 = 8 * nf + 2 * c2;
                int kc = nf >> 1;
                #pragma unroll
                for (int h = 0; h < 2; h++) {
                    int i = r0 + 8 * h;
                    int s0 = i + j0, s1 = s0 + 1;
                    float x0 = accA[nf][2 * h] + ((s0 < 64) ? gc : gn)[i * GS + (s0 & 63)];
                    float x1 = accA[nf][2 * h + 1] + ((s1 < 64) ? gc : gn)[i * GS + (s1 & 63)];
                    size_t gidx = ((size_t)b * L_ + l0 + i) * L_ + t * 64 + j0;
                    if (mode == 0) {
                        unsigned short mv = *(const unsigned short*)(maskp + gidx);
                        if (mv & 0x00ff) x0 = -CUDART_INF_F;
                        if (mv & 0xff00) x1 = -CUDART_INF_F;
                    } else {
                        uint2 mv = *(const uint2*)((const uint32_t*)maskp + gidx);
                        if (mv.x) x0 = -CUDART_INF_F;
                        if (mv.y) x1 = -CUDART_INF_F;
                    }
                    *(float2*)(attn + gidx) = make_float2(x0, x1);
                    float e0 = __expf(x0), e1 = __expf(x1);
                    run_s[h] += e0 + e1;
                    int reg = 2 * (nf & 1) + h;
                    Ph[kc][reg] = pk2(e0, e1);
                    Pl[kc][reg] = pk2(bfres(e0), bfres(e1));
                }
            }
            // PV: accO += p @ V(t)   (V buffer t&1; 3-term split)
            int oV = (t & 1) ? O_R : O_VA;
            #pragma unroll
            for (int kc = 0; kc < 4; kc++)
                #pragma unroll
                for (int np = 0; np < 4; np++) {
                    uint32_t bh[4], bl_[4];
                    LDSM4T(bh, adBT(oV, np, kc, 1));
                    MMA(accO[2 * np], Ph[kc], bh);     MMA(accO[2 * np], Pl[kc], bh);
                    MMA(accO[2 * np + 1], Ph[kc], bh + 2); MMA(accO[2 * np + 1], Pl[kc], bh + 2);
                    LDSM4T(bl_, adBT(oV, np, kc, 0));
                    MMA(accO[2 * np], Ph[kc], bl_);    MMA(accO[2 * np + 1], Ph[kc], bl_ + 2);
                }
        }
    }

    // ---- S-warps: reduce row sums (quad-local), store O and g_S ----
    if (isS) {
        float invS[2];
        #pragma unroll
        for (int h = 0; h < 2; h++) {
            float s = run_s[h];
            s += __shfl_xor_sync(0xffffffffu, s, 1);
            s += __shfl_xor_sync(0xffffffffu, s, 2);
            invS[h] = 1.f / s;
            if (c2 == 0) g_S[(size_t)b * L_ + l0 + r0 + 8 * h] = s;
        }
        #pragma unroll
        for (int g = 0; g < 8; g++) {
            int j0 = 8 * g + 2 * c2;
            #pragma unroll
            for (int h = 0; h < 2; h++) {
                int i = r0 + 8 * h;
                *(float2*)(out + ((size_t)b * L_ + l0 + i) * 64 + j0) =
                    make_float2(accO[g][2 * h] * invS[h], accO[g][2 * h + 1] * invS[h]);
            }
        }
    }
}

// ---- pass 2: attn logits -> probabilities, fully coalesced ----
__global__ __launch_bounds__(256)
void norm_kernel(float* __restrict__ attn) {
    int gid = blockIdx.x * 256 + threadIdx.x;
    int row = gid >> 6;             // 64 threads per 1024-float row
    int seg = gid & 63;
    float invS = 1.f / g_S[row];
    float* p = attn + (size_t)row * L_ + seg * 16;
    #pragma unroll
    for (int e = 0; e < 4; e++) {
        float4 x = *(float4*)(p + 4 * e);
        x.x = __expf(x.x) * invS; x.y = __expf(x.y) * invS;
        x.z = __expf(x.z) * invS; x.w = __expf(x.w) * invS;
        *(float4*)(p + 4 * e) = x;
    }
}

extern "C" void kernel_launch(void* const* d_in, const int* in_sizes, int n_in,
                              void* d_out, int out_size) {
    const float* q = (const float*)d_in[0];
    const float* k = (const float*)d_in[1];
    const float* v = (const float*)d_in[2];
    const float* pos = (const float*)d_in[3];
    const char* msk = (const char*)d_in[4];
    float* out = (float*)d_out;
    float* attn = out + (size_t)B_ * L_ * 64;

    cudaFuncSetAttribute(fused_fa_kernel,
                         cudaFuncAttributeMaxDynamicSharedMemorySize, SMEMB);
    fused_fa_kernel<<<dim3(16, B_), 256, SMEMB>>>(q, k, v, pos, msk, out, attn);
    norm_kernel<<<(B_ * L_ * L_) / (256 * 16), 256>>>(attn);
}